// round 8
// baseline (speedup 1.0000x reference)
#include <cuda_runtime.h>

// Problem constants (fixed shapes from reference setup_inputs)
#define BATCH   4
#define NCH     4      // segmentation channels (class 0 = background)
#define NCLS    3      // foreground classes 1..3
#define NPTS    8192   // W*H = 64*128
#define CHUNK   256
#define VCAP    4096   // valid-point list capacity (mean 2048, sigma ~39)
#define RADIUS2 9.0f

// Spatial grid over kept points: 4m cells, 96x96 interior covering [-192,192),
// padded to 98x98 (empty border) so the 3x3 probe needs no bounds checks.
// A 4m cell holds at most 4 points pairwise > 3m apart -> capacity 4 exact.
#define GC      96
#define GP      98
#define GPCELLS (GP * GP)
#define GINV    0.25f
#define GORG    192.0f

// Dynamic shared layout (byte offsets):
//   float2         kept[VCAP]          @ 0        32768
//   unsigned short cellidx[GPCELLS*4]  @ 32768    76832  (0xFFFF sentinel)
//   int            counts[GPCELLS]     @ 109600   38416
//   float2         vxy[VCAP]           @ 148016   32768
//   unsigned short vidx[VCAP]          @ 180784    8192
//   unsigned       col[CHUNK*8]        @ 188976    8192  (16B-aligned)
static const int SMEM_BYTES = 197168;

__global__ __launch_bounds__(CHUNK, 1)
void radius_nms_kernel(const float* __restrict__ seg,
                       const float* __restrict__ lidar,
                       float* __restrict__ out) {
    extern __shared__ char smem_raw[];
    float2*         kept    = (float2*)smem_raw;
    unsigned short* cellidx = (unsigned short*)(smem_raw + 32768);
    int*            counts  = (int*)(smem_raw + 109600);
    float2*         vxy     = (float2*)(smem_raw + 148016);
    unsigned short* vidx    = (unsigned short*)(smem_raw + 180784);
    unsigned*       col     = (unsigned*)(smem_raw + 188976);

    __shared__ int warpsum[2][8];
    __shared__ unsigned amask[8];
    __shared__ unsigned keepbits[8];
    __shared__ int kcount;

    const int blk  = blockIdx.x;          // 0..11
    const int b    = blk / NCLS;
    const int cls  = (blk % NCLS) + 1;    // foreground class 1..3
    const int t    = threadIdx.x;
    const int warp = t >> 5;
    const int lane = t & 31;

    const float* segb = seg + (size_t)b * NCH * NPTS;
    const float* lx   = lidar + (size_t)b * 5 * NPTS;   // lidar ch 0 = x
    const float* ly   = lx + NPTS;                       // ch 1 = y

    float* coord_out = out + (size_t)(b * NCLS + (cls - 1)) * NPTS * 2;
    float* keep_out  = out + (size_t)BATCH * NCLS * NPTS * 2
                           + (size_t)(b * NCLS + (cls - 1)) * NPTS;

    // init grid (sentinel indices) + counters
    {
        unsigned* ci32 = (unsigned*)cellidx;             // 2 slots per word
        for (int i = t; i < GPCELLS * 2; i += CHUNK) ci32[i] = 0xffffffffu;
        for (int i = t; i < GPCELLS; i += CHUNK) counts[i] = 0;
        if (t == 0) kcount = 0;
    }

    // =====================================================================
    // PASS 1: argmax, zero all outputs, ordered compaction of valid points
    // =====================================================================
    float ps0 = segb[0 * NPTS + t];
    float ps1 = segb[1 * NPTS + t];
    float ps2 = segb[2 * NPTS + t];
    float ps3 = segb[3 * NPTS + t];
    float px  = lx[t];
    float py  = ly[t];

    int vbase = 0;                                       // same on all threads
    int par = 0;
    for (int base = 0; base < NPTS; base += CHUNK, par ^= 1) {
        const int n = base + t;
        const float s0 = ps0, s1 = ps1, s2 = ps2, s3 = ps3;
        const float x = px, y = py;

        if (base + CHUNK < NPTS) {                       // prefetch next chunk
            const int m = n + CHUNK;
            ps0 = segb[0 * NPTS + m];
            ps1 = segb[1 * NPTS + m];
            ps2 = segb[2 * NPTS + m];
            ps3 = segb[3 * NPTS + m];
            px  = lx[m];
            py  = ly[m];
        }

        // argmax class (first-max tie-break, like jnp.argmax)
        int   am = 0; float mv = s0;
        if (s1 > mv) { mv = s1; am = 1; }
        if (s2 > mv) { mv = s2; am = 2; }
        if (s3 > mv) { mv = s3; am = 3; }
        const bool valid = (am == cls);

        // zero outputs (kept points overwritten in pass 2)
        keep_out[n] = 0.0f;
        reinterpret_cast<float2*>(coord_out)[n] = make_float2(0.0f, 0.0f);

        // ordered compaction (ping-pong warpsum -> 1 barrier per chunk)
        unsigned bal = __ballot_sync(0xffffffffu, valid);
        if (lane == 0) warpsum[par][warp] = __popc(bal);
        __syncthreads();
        int woff = vbase, tot = 0;
        #pragma unroll
        for (int w = 0; w < 8; w++) {
            int ws = warpsum[par][w];
            if (w < warp) woff += ws;
            tot += ws;
        }
        const int pos = woff + __popc(bal & ((1u << lane) - 1u));
        if (valid && pos < VCAP) {
            vxy[pos] = make_float2(x, y);
            vidx[pos] = (unsigned short)n;
        }
        vbase += tot;
    }
    const int V = vbase < VCAP ? vbase : VCAP;
    __syncthreads();                                     // vlist + grid visible

    // =====================================================================
    // PASS 2: chunked greedy NMS over the compacted valid-point list
    // =====================================================================
    for (int vb = 0; vb < V; vb += CHUNK) {
        const int tv = vb + t;
        const bool inr = tv < V;                         // vxy cap-safe always
        const float2 p = vxy[tv];
        const float x = p.x, y = p.y;

        // grid cell (interior coords clamp into [0,95]; NaN-safe)
        int gx = (int)floorf((x + GORG) * GINV);
        int gy = (int)floorf((y + GORG) * GINV);
        gx = min(max(gx, 0), GC - 1);
        gy = min(max(gy, 0), GC - 1);
        const int ccell = (gy + 1) * GP + (gx + 1);

        // BRANCHLESS probe: 3x3 cells x 4 slots, sentinel-gated, full MLP
        bool sup = false;
        #pragma unroll
        for (int dy = -1; dy <= 1; dy++) {
            #pragma unroll
            for (int dx = -1; dx <= 1; dx++) {
                const int cell = ccell + dy * GP + dx;
                uint2 s = *(const uint2*)&cellidx[cell * 4];
                const unsigned id0 = s.x & 0xffffu, id1 = s.x >> 16;
                const unsigned id2 = s.y & 0xffffu, id3 = s.y >> 16;
                float2 k0 = kept[id0 & 0x0fffu];
                float2 k1 = kept[id1 & 0x0fffu];
                float2 k2 = kept[id2 & 0x0fffu];
                float2 k3 = kept[id3 & 0x0fffu];
                float d0 = (x-k0.x)*(x-k0.x) + (y-k0.y)*(y-k0.y);
                float d1 = (x-k1.x)*(x-k1.x) + (y-k1.y)*(y-k1.y);
                float d2 = (x-k2.x)*(x-k2.x) + (y-k2.y)*(y-k2.y);
                float d3 = (x-k3.x)*(x-k3.x) + (y-k3.y)*(y-k3.y);
                sup |= (id0 != 0xffffu) & (d0 <= RADIUS2);
                sup |= (id1 != 0xffffu) & (d1 <= RADIUS2);
                sup |= (id2 != 0xffffu) & (d2 <= RADIUS2);
                sup |= (id3 != 0xffffu) & (d3 <= RADIUS2);
            }
        }
        const bool alive = inr && !sup;

        unsigned bal = __ballot_sync(0xffffffffu, alive);
        if (lane == 0) amask[warp] = bal;
        __syncthreads();                                 // Q1

        // conflict COLUMNS (t-indexed) over alive set-bits only.
        // amask identical across warp -> uniform loops, no divergence.
        {
            const float xt = alive ? x : 1.0e30f;
            const float yt = alive ? y : 1.0e30f;
            #pragma unroll
            for (int w = 0; w < 8; w++) {
                unsigned m = amask[w];
                while (m) {
                    const int k = __ffs(m) - 1; m &= m - 1;
                    const int i = (w << 5) + k;
                    const float2 q = vxy[vb + i];        // LDS broadcast
                    float dxx = xt - q.x, dyy = yt - q.y;
                    bool c = (t > i) && (dxx * dxx + dyy * dyy <= RADIUS2);
                    unsigned mm = __ballot_sync(0xffffffffu, c);
                    if (lane == 0) col[i * 8 + warp] = mm;
                }
            }
        }
        __syncthreads();                                 // Q2

        // serial greedy (thread 0): branchless body, t-indexed bitsets,
        // iterate alive set-bits in ascending t (= original index) order.
        if (t == 0) {
            unsigned supp[8] = {0,0,0,0,0,0,0,0};
            #pragma unroll
            for (int w = 0; w < 8; w++) {
                unsigned m = amask[w];
                unsigned kbw = 0;
                while (m) {
                    const int k = __ffs(m) - 1; m &= m - 1;
                    const unsigned kbit = (~supp[w] >> k) & 1u;
                    kbw |= kbit << k;
                    const unsigned msk = (unsigned)(0u - kbit);
                    const uint4* c4 = (const uint4*)&col[((w << 5) + k) * 8];
                    uint4 a = c4[0], bb = c4[1];
                    supp[0] |= msk & a.x;  supp[1] |= msk & a.y;
                    supp[2] |= msk & a.z;  supp[3] |= msk & a.w;
                    supp[4] |= msk & bb.x; supp[5] |= msk & bb.y;
                    supp[6] |= msk & bb.z; supp[7] |= msk & bb.w;
                }
                keepbits[w] = kbw;
            }
        }
        __syncthreads();                                 // Q3

        // resolve keep, append to kept[] + cell insert, scatter outputs
        const bool keepme = alive && ((keepbits[t >> 5] >> (t & 31)) & 1u);
        if (keepme) {
            int kpos = atomicAdd(&kcount, 1);
            kept[kpos] = make_float2(x, y);
            int slot = atomicAdd(&counts[ccell], 1);     // slot < 4 provably
            cellidx[ccell * 4 + slot] = (unsigned short)kpos;
            const int n0 = vidx[tv];
            keep_out[n0] = 1.0f;
            reinterpret_cast<float2*>(coord_out)[n0] = make_float2(x, y);
        }
        __syncthreads();                                 // Q4 (inserts visible)
    }
}

extern "C" void kernel_launch(void* const* d_in, const int* in_sizes, int n_in,
                              void* d_out, int out_size) {
    (void)in_sizes; (void)n_in; (void)out_size;
    const float* seg   = (const float*)d_in[0];
    const float* lidar = (const float*)d_in[1];
    float* out = (float*)d_out;

    cudaFuncSetAttribute(radius_nms_kernel,
                         cudaFuncAttributeMaxDynamicSharedMemorySize, SMEM_BYTES);
    radius_nms_kernel<<<BATCH * NCLS, CHUNK, SMEM_BYTES>>>(seg, lidar, out);
}

// round 9
// speedup vs baseline: 2.4587x; 2.4587x over previous
#include <cuda_runtime.h>

// Problem constants (fixed shapes from reference setup_inputs)
#define BATCH   4
#define NCH     4      // segmentation channels (class 0 = background)
#define NCLS    3      // foreground classes 1..3
#define NPTS    8192   // W*H = 64*128
#define CHUNK   256    // points per NMS chunk (small keeps candidates low)
#define THREADS 512    // warps 0-7: point owners; warps 8-15: probe helpers
#define MAXK    8192
#define RADIUS2 9.0f

// Spatial grid over kept points: 4m cells, 96x96 interior covering [-192,192),
// padded to 98x98 (empty border) -> 3x3 probe needs no bounds checks.
// A 4m cell holds at most 4 points pairwise > 3m apart (pigeonhole over
// 2x2m quadrants) -> slot capacity 4 is provably exact. Coords are N(0,30m);
// clamp at +-192m = 6.4 sigma never triggers in practice, and clamping is
// monotone so cell adjacency of close pairs is preserved regardless.
#define GC      96
#define GP      98
#define GPCELLS (GP * GP)
#define GINV    0.25f
#define GORG    192.0f

// Dynamic shared layout (byte offsets):
//   float2         kept[MAXK]          @ 0        65536
//   unsigned short cellidx[GPCELLS*4]  @ 65536    76832  (0xFFFF sentinel)
//   int            counts[GPCELLS]     @ 142368   38416
//   float2         ccxy[CHUNK]         @ 180784    2048  (compacted candidates)
//   unsigned       col[CHUNK*8]        @ 182832    8192  (rows, 16B-aligned)
static const int SMEM_BYTES = 191024;

// Branchless probe of one padded-grid cell; accumulates into 'sup'.
#define PROBE_CELL(CELL)                                                    \
    do {                                                                    \
        uint2 s = *(const uint2*)&cellidx[(CELL) * 4];                      \
        const unsigned i0 = s.x & 0xffffu, i1 = s.x >> 16;                  \
        const unsigned i2 = s.y & 0xffffu, i3 = s.y >> 16;                  \
        float2 k0 = kept[i0 & 0x1fffu];                                     \
        float2 k1 = kept[i1 & 0x1fffu];                                     \
        float2 k2 = kept[i2 & 0x1fffu];                                     \
        float2 k3 = kept[i3 & 0x1fffu];                                     \
        float d0 = (x-k0.x)*(x-k0.x) + (y-k0.y)*(y-k0.y);                   \
        float d1 = (x-k1.x)*(x-k1.x) + (y-k1.y)*(y-k1.y);                   \
        float d2 = (x-k2.x)*(x-k2.x) + (y-k2.y)*(y-k2.y);                   \
        float d3 = (x-k3.x)*(x-k3.x) + (y-k3.y)*(y-k3.y);                   \
        sup |= (i0 != 0xffffu) & (d0 <= RADIUS2);                           \
        sup |= (i1 != 0xffffu) & (d1 <= RADIUS2);                           \
        sup |= (i2 != 0xffffu) & (d2 <= RADIUS2);                           \
        sup |= (i3 != 0xffffu) & (d3 <= RADIUS2);                           \
    } while (0)

__global__ __launch_bounds__(THREADS, 1)
void radius_nms_kernel(const float* __restrict__ seg,
                       const float* __restrict__ lidar,
                       float* __restrict__ out) {
    extern __shared__ char smem_raw[];
    float2*         kept    = (float2*)smem_raw;
    unsigned short* cellidx = (unsigned short*)(smem_raw + 65536);
    int*            counts  = (int*)(smem_raw + 142368);
    float2*         ccxy    = (float2*)(smem_raw + 180784);
    unsigned*       col     = (unsigned*)(smem_raw + 182832);

    __shared__ unsigned char supB[CHUNK];
    __shared__ int warpsum[8];
    __shared__ unsigned keepbits[8];
    __shared__ int kcount;

    const int blk  = blockIdx.x;          // 0..11
    const int b    = blk / NCLS;
    const int cls  = (blk % NCLS) + 1;    // foreground class 1..3
    const int t    = threadIdx.x;
    const int tp   = t & (CHUNK - 1);     // owned point slot (both halves)
    const bool low = t < CHUNK;
    const int warp = t >> 5;
    const int lane = t & 31;

    const float* segb = seg + (size_t)b * NCH * NPTS;
    const float* lx   = lidar + (size_t)b * 5 * NPTS;   // lidar ch 0 = x
    const float* ly   = lx + NPTS;                       // ch 1 = y

    float* coord_out = out + (size_t)(b * NCLS + (cls - 1)) * NPTS * 2;
    float* keep_out  = out + (size_t)BATCH * NCLS * NPTS * 2
                           + (size_t)(b * NCLS + (cls - 1)) * NPTS;

    // init grid (sentinel indices) + counters
    {
        unsigned* ci32 = (unsigned*)cellidx;             // 2 slots per word
        for (int i = t; i < GPCELLS * 2; i += THREADS) ci32[i] = 0xffffffffu;
        for (int i = t; i < GPCELLS; i += THREADS) counts[i] = 0;
        if (t == 0) kcount = 0;
    }

    // per-half register prefetch of chunk 0
    float ps0 = 0, ps1 = 0, ps2 = 0, ps3 = 0;
    if (low) {
        ps0 = segb[0 * NPTS + tp];
        ps1 = segb[1 * NPTS + tp];
        ps2 = segb[2 * NPTS + tp];
        ps3 = segb[3 * NPTS + tp];
    }
    float px = lx[tp];
    float py = ly[tp];

    __syncthreads();

    for (int base = 0; base < NPTS; base += CHUNK) {
        const int n = base + tp;
        const float x = px, y = py;
        const float s0 = ps0, s1 = ps1, s2 = ps2, s3 = ps3;

        if (base + CHUNK < NPTS) {                       // prefetch next chunk
            const int m = n + CHUNK;
            if (low) {
                ps0 = segb[0 * NPTS + m];
                ps1 = segb[1 * NPTS + m];
                ps2 = segb[2 * NPTS + m];
                ps3 = segb[3 * NPTS + m];
            }
            px = lx[m];
            py = ly[m];
        }

        // grid cell of own point (both halves compute independently)
        int gx = (int)floorf((x + GORG) * GINV);
        int gy = (int)floorf((y + GORG) * GINV);
        gx = min(max(gx, 0), GC - 1);
        gy = min(max(gy, 0), GC - 1);
        const int ccell = (gy + 1) * GP + (gx + 1);      // padded index

        // ---- split branchless probe: low half 5 cells, high half 4 cells
        bool sup = false;
        if (low) {
            PROBE_CELL(ccell - GP - 1);
            PROBE_CELL(ccell - GP);
            PROBE_CELL(ccell - GP + 1);
            PROBE_CELL(ccell - 1);
            PROBE_CELL(ccell);
        } else {
            PROBE_CELL(ccell + 1);
            PROBE_CELL(ccell + GP - 1);
            PROBE_CELL(ccell + GP);
            PROBE_CELL(ccell + GP + 1);
            supB[tp] = (unsigned char)sup;
        }
        __syncthreads();                                 // B0: supB ready

        // ---- low half: validity, combine sup, ballot-scan candidates
        bool alive = false;
        unsigned bal = 0;
        if (low) {
            int   am = 0; float mv = s0;                 // jnp.argmax tie-break
            if (s1 > mv) { mv = s1; am = 1; }
            if (s2 > mv) { mv = s2; am = 2; }
            if (s3 > mv) { mv = s3; am = 3; }
            const bool valid = (am == cls);
            alive = valid && !(sup | (bool)supB[tp]);
            bal = __ballot_sync(0xffffffffu, alive);
            if (lane == 0) warpsum[warp] = __popc(bal);
        }
        __syncthreads();                                 // B1: warpsum ready

        int A = 0, pos = 0;
        if (low) {
            int woff = 0;
            #pragma unroll
            for (int w = 0; w < 8; w++) {
                int ws = warpsum[w];
                if (w < warp) woff += ws;
                A += ws;
            }
            pos = woff + __popc(bal & ((1u << lane) - 1u));
            if (alive) ccxy[pos] = make_float2(x, y);
        }
        __syncthreads();                                 // B2: ccxy ready

        // ---- ROW-PARALLEL conflict rows: each alive thread builds its own
        //      lower-triangular row (bits j < pos) over candidates 0..A-1.
        //      ccxy[j] reads are warp-broadcast; word regs constant-indexed.
        if (low && alive) {
            unsigned r[8] = {0,0,0,0,0,0,0,0};
            #pragma unroll
            for (int w = 0; w < 8; w++) {
                const int b0 = w << 5;
                if (b0 >= A) break;
                const int nb = (A - b0) < 32 ? (A - b0) : 32;
                unsigned rw = 0;
                for (int k = 0; k < nb; k++) {
                    const float2 q = ccxy[b0 + k];
                    const float dxx = x - q.x, dyy = y - q.y;
                    const unsigned c =
                        ((b0 + k) < pos) & (dxx * dxx + dyy * dyy <= RADIUS2);
                    rw |= c << k;
                }
                r[w] = rw;
            }
            uint4* dst = (uint4*)&col[pos * 8];
            dst[0] = make_uint4(r[0], r[1], r[2], r[3]);
            dst[1] = make_uint4(r[4], r[5], r[6], r[7]);
        }
        __syncthreads();                                 // B3: rows ready

        // ---- serial greedy (thread 0), ROW formulation:
        //      keep i iff no earlier KEPT candidate conflicts: row_i & kb == 0
        if (t == 0) {
            unsigned kb[8] = {0,0,0,0,0,0,0,0};
            #pragma unroll
            for (int w = 0; w < 8; w++) {
                const int b0 = w << 5;
                if (b0 >= A) break;
                const int nb = (A - b0) < 32 ? (A - b0) : 32;
                for (int k = 0; k < nb; k++) {
                    const uint4* c4 = (const uint4*)&col[(b0 + k) * 8];
                    uint4 a = c4[0], bb = c4[1];
                    unsigned hit = (a.x  & kb[0]) | (a.y  & kb[1])
                                 | (a.z  & kb[2]) | (a.w  & kb[3])
                                 | (bb.x & kb[4]) | (bb.y & kb[5])
                                 | (bb.z & kb[6]) | (bb.w & kb[7]);
                    kb[w] |= (unsigned)(hit == 0) << k;
                }
            }
            #pragma unroll
            for (int w = 0; w < 8; w++) keepbits[w] = kb[w];
        }
        __syncthreads();                                 // B4: keepbits ready

        // ---- resolve keep, append to kept[] + cell insert, write outputs
        if (low) {
            const bool keepme =
                alive && ((keepbits[pos >> 5] >> (pos & 31)) & 1u);
            if (keepme) {
                int kpos = atomicAdd(&kcount, 1);
                kept[kpos] = make_float2(x, y);
                int slot = atomicAdd(&counts[ccell], 1); // slot < 4 provably
                cellidx[ccell * 4 + slot] = (unsigned short)kpos;
            }
            const float kf = keepme ? 1.0f : 0.0f;
            keep_out[n] = kf;
            reinterpret_cast<float2*>(coord_out)[n] = make_float2(x*kf, y*kf);
        }
        __syncthreads();                                 // B5: inserts visible
    }
}

extern "C" void kernel_launch(void* const* d_in, const int* in_sizes, int n_in,
                              void* d_out, int out_size) {
    (void)in_sizes; (void)n_in; (void)out_size;
    const float* seg   = (const float*)d_in[0];
    const float* lidar = (const float*)d_in[1];
    float* out = (float*)d_out;

    cudaFuncSetAttribute(radius_nms_kernel,
                         cudaFuncAttributeMaxDynamicSharedMemorySize, SMEM_BYTES);
    radius_nms_kernel<<<BATCH * NCLS, THREADS, SMEM_BYTES>>>(seg, lidar, out);
}